// round 1
// baseline (speedup 1.0000x reference)
#include <cuda_runtime.h>
#include <math.h>

#define BATCH 4
#define C 512
#define HW 4096
#define G 32
#define CPG 16
#define EPS 1e-5f

// Scratch (static device memory — no allocations)
__device__ float g_h[(size_t)BATCH * C * HW];   // 32 MB  groupnorm output
__device__ float g_q[(size_t)BATCH * C * HW];   // 32 MB
__device__ float g_k[(size_t)BATCH * C * HW];   // 32 MB
__device__ float g_v[(size_t)BATCH * C * HW];   // 32 MB
__device__ float g_s[(size_t)BATCH * HW * HW];  // 256 MB scores / attn
__device__ float g_o[(size_t)BATCH * C * HW];   // 32 MB  attention output

// ---------------------------------------------------------------------------
// GroupNorm: one block per (batch, group). Reduce 16*4096 elems, then apply.
// ---------------------------------------------------------------------------
__global__ void gn_kernel(const float* __restrict__ x, const float* __restrict__ w,
                          const float* __restrict__ b, float* __restrict__ out) {
    const int batch = blockIdx.x / G;
    const int g = blockIdx.x % G;
    const size_t base = ((size_t)batch * C + (size_t)g * CPG) * HW;
    const float* xp = x + base;

    float sum = 0.f, sq = 0.f;
    for (int i = threadIdx.x; i < CPG * HW; i += blockDim.x) {
        float v = xp[i];
        sum += v;
        sq += v * v;
    }
    __shared__ float s1[32], s2[32];
#pragma unroll
    for (int o = 16; o; o >>= 1) {
        sum += __shfl_xor_sync(~0u, sum, o);
        sq += __shfl_xor_sync(~0u, sq, o);
    }
    const int lane = threadIdx.x & 31, wid = threadIdx.x >> 5;
    if (lane == 0) { s1[wid] = sum; s2[wid] = sq; }
    __syncthreads();
    const int nw = blockDim.x >> 5;
    if (wid == 0) {
        sum = lane < nw ? s1[lane] : 0.f;
        sq = lane < nw ? s2[lane] : 0.f;
#pragma unroll
        for (int o = 16; o; o >>= 1) {
            sum += __shfl_xor_sync(~0u, sum, o);
            sq += __shfl_xor_sync(~0u, sq, o);
        }
        if (lane == 0) {
            const float inv_n = 1.f / (float)(CPG * HW);
            float m = sum * inv_n;
            float var = sq * inv_n - m * m;
            s1[0] = m;
            s2[0] = rsqrtf(var + EPS);
        }
    }
    __syncthreads();
    const float m = s1[0], r = s2[0];
    for (int i = threadIdx.x; i < CPG * HW; i += blockDim.x) {
        int c = g * CPG + i / HW;
        out[base + i] = (xp[i] - m) * r * w[c] + b[c];
    }
}

// ---------------------------------------------------------------------------
// Generic batched SGEMM: Cout[m,n] = alpha * sum_k Aop[m,k]*Bop[k,n] (+bias[m]) (+res[m,n])
//   TA: A stored [K, M] (A[m,k] = A[k*M + m]), else [M, K]
//   TB: B stored [N, K] (B[k,n] = B[n*K + k]), else [K, N]
// 128x128 tile, BK=8, 256 threads, 8x8 per thread. All dims multiples of 128.
// ---------------------------------------------------------------------------
template <bool TA, bool TB, bool BIAS, bool RES>
__global__ __launch_bounds__(256) void gemm_kernel(
    const float* __restrict__ A, const float* __restrict__ B,
    const float* __restrict__ bias, const float* __restrict__ res,
    float* __restrict__ Cout, int M, int N, int K, float alpha,
    size_t sA, size_t sB, size_t sC, size_t sRes) {
    A += (size_t)blockIdx.z * sA;
    B += (size_t)blockIdx.z * sB;
    Cout += (size_t)blockIdx.z * sC;
    if (RES) res += (size_t)blockIdx.z * sRes;

    const int bm = blockIdx.y * 128;
    const int bn = blockIdx.x * 128;

    __shared__ float As[8][128];
    __shared__ float Bs[8][128];

    const int tid = threadIdx.x;
    const int tx = tid & 15;   // col group
    const int ty = tid >> 4;   // row group

    float acc[8][8];
#pragma unroll
    for (int i = 0; i < 8; i++)
#pragma unroll
        for (int j = 0; j < 8; j++) acc[i][j] = 0.f;

    for (int k0 = 0; k0 < K; k0 += 8) {
        if (TA) {
            const int k = tid >> 5, m = (tid & 31) * 4;
            const float4 v = *reinterpret_cast<const float4*>(&A[(size_t)(k0 + k) * M + bm + m]);
            *reinterpret_cast<float4*>(&As[k][m]) = v;
        } else {
            const int m = tid >> 1, k = (tid & 1) * 4;
            const float4 v = *reinterpret_cast<const float4*>(&A[(size_t)(bm + m) * K + k0 + k]);
            As[k][m] = v.x; As[k + 1][m] = v.y; As[k + 2][m] = v.z; As[k + 3][m] = v.w;
        }
        if (TB) {
            const int n = tid >> 1, k = (tid & 1) * 4;
            const float4 v = *reinterpret_cast<const float4*>(&B[(size_t)(bn + n) * K + k0 + k]);
            Bs[k][n] = v.x; Bs[k + 1][n] = v.y; Bs[k + 2][n] = v.z; Bs[k + 3][n] = v.w;
        } else {
            const int k = tid >> 5, n = (tid & 31) * 4;
            const float4 v = *reinterpret_cast<const float4*>(&B[(size_t)(k0 + k) * N + bn + n]);
            *reinterpret_cast<float4*>(&Bs[k][n]) = v;
        }
        __syncthreads();
#pragma unroll
        for (int k = 0; k < 8; k++) {
            float a[8], bb[8];
            *reinterpret_cast<float4*>(&a[0]) = *reinterpret_cast<const float4*>(&As[k][ty * 8]);
            *reinterpret_cast<float4*>(&a[4]) = *reinterpret_cast<const float4*>(&As[k][ty * 8 + 4]);
            *reinterpret_cast<float4*>(&bb[0]) = *reinterpret_cast<const float4*>(&Bs[k][tx * 8]);
            *reinterpret_cast<float4*>(&bb[4]) = *reinterpret_cast<const float4*>(&Bs[k][tx * 8 + 4]);
#pragma unroll
            for (int i = 0; i < 8; i++)
#pragma unroll
                for (int j = 0; j < 8; j++) acc[i][j] += a[i] * bb[j];
        }
        __syncthreads();
    }

#pragma unroll
    for (int i = 0; i < 8; i++) {
        const int row = bm + ty * 8 + i;
        const float bv = BIAS ? bias[row] : 0.f;
#pragma unroll
        for (int j = 0; j < 8; j += 4) {
            const int col = bn + tx * 8 + j;
            float4 o;
            o.x = alpha * acc[i][j] + bv;
            o.y = alpha * acc[i][j + 1] + bv;
            o.z = alpha * acc[i][j + 2] + bv;
            o.w = alpha * acc[i][j + 3] + bv;
            if (RES) {
                const float4 r = *reinterpret_cast<const float4*>(&res[(size_t)row * N + col]);
                o.x += r.x; o.y += r.y; o.z += r.z; o.w += r.w;
            }
            *reinterpret_cast<float4*>(&Cout[(size_t)row * N + col]) = o;
        }
    }
}

// ---------------------------------------------------------------------------
// Row softmax over 4096 elements. One block (256 threads) per row; 16/thread.
// ---------------------------------------------------------------------------
__global__ __launch_bounds__(256) void softmax_kernel(float* __restrict__ s) {
    float* row = s + (size_t)blockIdx.x * HW;
    const int t = threadIdx.x;
    float v[16];
    float mx = -1e30f;
#pragma unroll
    for (int i = 0; i < 16; i++) {
        v[i] = row[t + i * 256];
        mx = fmaxf(mx, v[i]);
    }
    __shared__ float shm[8];
    __shared__ float shs[8];
#pragma unroll
    for (int o = 16; o; o >>= 1) mx = fmaxf(mx, __shfl_xor_sync(~0u, mx, o));
    const int lane = t & 31, wid = t >> 5;
    if (lane == 0) shm[wid] = mx;
    __syncthreads();
    mx = shm[0];
#pragma unroll
    for (int i = 1; i < 8; i++) mx = fmaxf(mx, shm[i]);

    float sum = 0.f;
#pragma unroll
    for (int i = 0; i < 16; i++) {
        v[i] = __expf(v[i] - mx);
        sum += v[i];
    }
#pragma unroll
    for (int o = 16; o; o >>= 1) sum += __shfl_xor_sync(~0u, sum, o);
    if (lane == 0) shs[wid] = sum;
    __syncthreads();
    sum = 0.f;
#pragma unroll
    for (int i = 0; i < 8; i++) sum += shs[i];
    const float inv = 1.f / sum;
#pragma unroll
    for (int i = 0; i < 16; i++) row[t + i * 256] = v[i] * inv;
}

// ---------------------------------------------------------------------------
extern "C" void kernel_launch(void* const* d_in, const int* in_sizes, int n_in,
                              void* d_out, int out_size) {
    const float* x   = (const float*)d_in[0];
    const float* gnw = (const float*)d_in[1];
    const float* gnb = (const float*)d_in[2];
    const float* qw  = (const float*)d_in[3];
    const float* qb  = (const float*)d_in[4];
    const float* kw  = (const float*)d_in[5];
    const float* kb  = (const float*)d_in[6];
    const float* vw  = (const float*)d_in[7];
    const float* vb  = (const float*)d_in[8];
    const float* pw  = (const float*)d_in[9];
    const float* pb  = (const float*)d_in[10];
    float* out = (float*)d_out;

    float *h, *q, *k, *v, *s, *o;
    cudaGetSymbolAddress((void**)&h, g_h);
    cudaGetSymbolAddress((void**)&q, g_q);
    cudaGetSymbolAddress((void**)&k, g_k);
    cudaGetSymbolAddress((void**)&v, g_v);
    cudaGetSymbolAddress((void**)&s, g_s);
    cudaGetSymbolAddress((void**)&o, g_o);

    const size_t sBC = (size_t)C * HW;       // per-batch stride for [C, HW]
    const size_t sS = (size_t)HW * HW;       // per-batch stride for scores
    const float scale = 0.044194173824159216f;  // 512^-0.5

    // 1) GroupNorm
    gn_kernel<<<BATCH * G, 512>>>(x, gnw, gnb, h);

    dim3 blk(256);
    dim3 g_qkv(HW / 128, C / 128, BATCH);   // N=4096, M=512
    dim3 g_sc(HW / 128, HW / 128, BATCH);   // N=4096, M=4096

    // 2) q/k/v = W @ h + b
    gemm_kernel<false, false, true, false><<<g_qkv, blk>>>(qw, h, qb, nullptr, q, C, HW, C, 1.f, 0, sBC, sBC, 0);
    gemm_kernel<false, false, true, false><<<g_qkv, blk>>>(kw, h, kb, nullptr, k, C, HW, C, 1.f, 0, sBC, sBC, 0);
    gemm_kernel<false, false, true, false><<<g_qkv, blk>>>(vw, h, vb, nullptr, v, C, HW, C, 1.f, 0, sBC, sBC, 0);

    // 3) scores = q^T k * C^-0.5   [HW, HW]
    gemm_kernel<true, false, false, false><<<g_sc, blk>>>(q, k, nullptr, nullptr, s, HW, HW, C, scale, sBC, sBC, sS, 0);

    // 4) softmax rows
    softmax_kernel<<<BATCH * HW, 256>>>(s);

    // 5) o[d, q] = sum_k v[d, k] * attn[q, k]   (B transposed)
    gemm_kernel<false, true, false, false><<<g_qkv, blk>>>(v, s, nullptr, nullptr, o, C, HW, HW, 1.f, sBC, sS, sBC, 0);

    // 6) out = x + pw @ o + pb
    gemm_kernel<false, false, true, true><<<g_qkv, blk>>>(pw, o, pb, x, out, C, HW, C, 1.f, 0, sBC, sBC, sBC);
}

// round 6
// speedup vs baseline: 3.4624x; 3.4624x over previous
#include <cuda_runtime.h>
#include <cstdint>
#include <math.h>

#define BATCH 4
#define C 512
#define HW 4096
#define G 32
#define CPG 16
#define EPS 1e-5f

// GEMM tiling
#define BM 128
#define BN 256
#define BK 32
#define STAGES 3
#define PAD 36                                   // floats per smem row (144B, 16B aligned, conflict-free)
#define STAGE_FLOATS ((BM + BN) * PAD)           // 13824
#define SMEM_BYTES (STAGES * STAGE_FLOATS * 4)   // 165888

// Scratch (static device memory — no allocations)
__device__ float g_ht[(size_t)BATCH * HW * C];   // groupnorm out, transposed [HW, C] (tf32-rounded)
__device__ float g_qt[(size_t)BATCH * HW * C];   // q^T [HW, C] (tf32-rounded)
__device__ float g_kt[(size_t)BATCH * HW * C];   // k^T [HW, C] (tf32-rounded)
__device__ float g_v [(size_t)BATCH * C * HW];   // v   [C, HW] (tf32-rounded)
__device__ float g_s [(size_t)BATCH * HW * HW];  // scores / attn [HWq, HWk]
__device__ float g_ot[(size_t)BATCH * HW * C];   // attn out, transposed [HW, C] (tf32-rounded)
__device__ float g_wr[(size_t)4 * C * C];        // tf32-rounded weights: qw, kw, vw, pw

// ---------------------------------------------------------------------------
// helpers
// ---------------------------------------------------------------------------
__device__ __forceinline__ uint32_t smem_u32(const void* p) {
    uint32_t a;
    asm("{ .reg .u64 t; cvta.to.shared.u64 t, %1; cvt.u32.u64 %0, t; }" : "=r"(a) : "l"(p));
    return a;
}

__device__ __forceinline__ uint32_t f2tf32(float f) {
    uint32_t u;
    asm("cvt.rna.tf32.f32 %0, %1;" : "=r"(u) : "f"(f));
    return u;
}
__device__ __forceinline__ float rnd_tf32(float f) { return __uint_as_float(f2tf32(f)); }

__device__ __forceinline__ void cp16(uint32_t dst, const void* src) {
    asm volatile("cp.async.cg.shared.global [%0], [%1], 16;" :: "r"(dst), "l"(src));
}

__device__ __forceinline__ void mma8(float* c, const uint32_t* a, const uint32_t* b) {
    asm volatile(
        "mma.sync.aligned.m16n8k8.row.col.f32.tf32.tf32.f32 "
        "{%0,%1,%2,%3}, {%4,%5,%6,%7}, {%8,%9}, {%0,%1,%2,%3};"
        : "+f"(c[0]), "+f"(c[1]), "+f"(c[2]), "+f"(c[3])
        : "r"(a[0]), "r"(a[1]), "r"(a[2]), "r"(a[3]), "r"(b[0]), "r"(b[1]));
}

// ---------------------------------------------------------------------------
// tf32 mma.sync GEMM: D[m,n] = alpha * sum_k A[m,k]*B[n,k] (+bias) (+res)
// A: [M,K] K-major, B: [N,K] K-major, out: [M,N] row-major.
// Block tile 128x256, 256 threads (8 warps, 2x4 grid of 64x64 warp tiles),
// BK=32, 3-stage cp.async pipeline. M%128==0, N%256==0, K%32==0, K/32>=3.
// Operands must be tf32-representable (pre-rounded) for exact tf32 math.
// ---------------------------------------------------------------------------
template <bool BROW, bool BCOL, bool RES, bool RND>
__global__ void __launch_bounds__(256, 1) tc_gemm(
    const float* __restrict__ A, const float* __restrict__ B,
    const float* __restrict__ bias, const float* __restrict__ res,
    float* __restrict__ Cout, int M, int N, int K, float alpha,
    size_t sA, size_t sB, size_t sC, size_t sRes) {
    extern __shared__ float smf[];
    const int tid = threadIdx.x;
    const int wid = tid >> 5, lane = tid & 31;
    const int wm = wid >> 2, wn = wid & 3;      // warp grid 2 (M) x 4 (N)
    const int gq = lane >> 2, tq = lane & 3;    // quad decomposition
    const int bm = blockIdx.y * BM;
    const int bn = blockIdx.x * BN;

    A += (size_t)blockIdx.z * sA;
    B += (size_t)blockIdx.z * sB;
    Cout += (size_t)blockIdx.z * sC;
    if (RES) res += (size_t)blockIdx.z * sRes;

    const uint32_t sb = smem_u32(smf);

    float acc[4][8][4];
#pragma unroll
    for (int i = 0; i < 4; i++)
#pragma unroll
        for (int j = 0; j < 8; j++)
#pragma unroll
            for (int l = 0; l < 4; l++) acc[i][j][l] = 0.f;

    const int nchunk = K / BK;

    // stage loader: A 1024 float4, B 2048 float4 over 256 threads
    auto load_stage = [&](int s, int c) {
        const int k0 = c * BK;
        const uint32_t st = sb + (uint32_t)(s * STAGE_FLOATS) * 4u;
#pragma unroll
        for (int t = 0; t < 4; t++) {
            const int i = tid + t * 256;
            const int row = i >> 3, q = i & 7;
            cp16(st + (uint32_t)(row * PAD + q * 4) * 4u,
                 &A[(size_t)(bm + row) * K + k0 + q * 4]);
        }
        const uint32_t stB = st + (uint32_t)(BM * PAD) * 4u;
#pragma unroll
        for (int t = 0; t < 8; t++) {
            const int i = tid + t * 256;
            const int row = i >> 3, q = i & 7;
            cp16(stB + (uint32_t)(row * PAD + q * 4) * 4u,
                 &B[(size_t)(bn + row) * K + k0 + q * 4]);
        }
    };

#pragma unroll
    for (int s = 0; s < STAGES - 1; s++) {
        load_stage(s, s);
        asm volatile("cp.async.commit_group;");
    }

    for (int c = 0; c < nchunk; c++) {
        asm volatile("cp.async.wait_group %0;" :: "n"(STAGES - 2));
        __syncthreads();

        const int nc = c + STAGES - 1;
        if (nc < nchunk) load_stage(nc % STAGES, nc);
        asm volatile("cp.async.commit_group;");

        const float* st = smf + (c % STAGES) * STAGE_FLOATS;
        const float* As = st;
        const float* Bs = st + BM * PAD;
#pragma unroll
        for (int k8 = 0; k8 < BK / 8; k8++) {
            uint32_t af[4][4], bf[8][2];
#pragma unroll
            for (int ms = 0; ms < 4; ms++) {
                const float* ap = As + (wm * 64 + ms * 16 + gq) * PAD + k8 * 8 + tq;
                af[ms][0] = __float_as_uint(ap[0]);
                af[ms][1] = __float_as_uint(ap[8 * PAD]);
                af[ms][2] = __float_as_uint(ap[4]);
                af[ms][3] = __float_as_uint(ap[8 * PAD + 4]);
            }
#pragma unroll
            for (int ns = 0; ns < 8; ns++) {
                const float* bp = Bs + (wn * 64 + ns * 8 + gq) * PAD + k8 * 8 + tq;
                bf[ns][0] = __float_as_uint(bp[0]);
                bf[ns][1] = __float_as_uint(bp[4]);
            }
#pragma unroll
            for (int ms = 0; ms < 4; ms++)
#pragma unroll
                for (int ns = 0; ns < 8; ns++) mma8(acc[ms][ns], af[ms], bf[ns]);
        }
    }

    // epilogue
#pragma unroll
    for (int ms = 0; ms < 4; ms++) {
        const int r0 = bm + wm * 64 + ms * 16 + gq;
        const int r1 = r0 + 8;
        const float bv0 = BROW ? bias[r0] : 0.f;
        const float bv1 = BROW ? bias[r1] : 0.f;
#pragma unroll
        for (int ns = 0; ns < 8; ns++) {
            const int col = bn + wn * 64 + ns * 8 + tq * 2;
            float2 o0, o1;
            o0.x = alpha * acc[ms][ns][0] + bv0;
            o0.y = alpha * acc[ms][ns][1] + bv0;
            o1.x = alpha * acc[ms][ns][2] + bv1;
            o1.y = alpha * acc[ms][ns][3] + bv1;
            if (BCOL) {
                const float bc0 = bias[col], bc1 = bias[col + 1];
                o0.x += bc0; o0.y += bc1;
                o1.x += bc0; o1.y += bc1;
            }
            if (RES) {
                const float2 q0 = *reinterpret_cast<const float2*>(&res[(size_t)r0 * N + col]);
                const float2 q1 = *reinterpret_cast<const float2*>(&res[(size_t)r1 * N + col]);
                o0.x += q0.x; o0.y += q0.y;
                o1.x += q1.x; o1.y += q1.y;
            }
            if (RND) {
                o0.x = rnd_tf32(o0.x); o0.y = rnd_tf32(o0.y);
                o1.x = rnd_tf32(o1.x); o1.y = rnd_tf32(o1.y);
            }
            *reinterpret_cast<float2*>(&Cout[(size_t)r0 * N + col]) = o0;
            *reinterpret_cast<float2*>(&Cout[(size_t)r1 * N + col]) = o1;
        }
    }
}

// ---------------------------------------------------------------------------
// tf32-round the four weight matrices into g_wr
// ---------------------------------------------------------------------------
__global__ void __launch_bounds__(256) round_w(const float* __restrict__ qw,
                                               const float* __restrict__ kw,
                                               const float* __restrict__ vw,
                                               const float* __restrict__ pw,
                                               float* __restrict__ o) {
    const int i = blockIdx.x * 256 + threadIdx.x;  // C*C = 262144 total
    o[i] = rnd_tf32(qw[i]);
    o[C * C + i] = rnd_tf32(kw[i]);
    o[2 * C * C + i] = rnd_tf32(vw[i]);
    o[3 * C * C + i] = rnd_tf32(pw[i]);
}

// ---------------------------------------------------------------------------
// GroupNorm -> transposed, tf32-rounded output hT [B, HW, C]
// ---------------------------------------------------------------------------
__global__ void __launch_bounds__(512) gn_kernel(const float* __restrict__ x,
                                                 const float* __restrict__ w,
                                                 const float* __restrict__ b,
                                                 float* __restrict__ hT) {
    const int batch = blockIdx.x / G;
    const int g = blockIdx.x % G;
    const float* xp = x + ((size_t)batch * C + (size_t)g * CPG) * HW;

    float sum = 0.f, sq = 0.f;
    for (int i = threadIdx.x; i < CPG * HW; i += blockDim.x) {
        const float v = xp[i];
        sum += v; sq += v * v;
    }
    __shared__ float s1[32], s2[32];
#pragma unroll
    for (int o = 16; o; o >>= 1) {
        sum += __shfl_xor_sync(~0u, sum, o);
        sq += __shfl_xor_sync(~0u, sq, o);
    }
    const int lane = threadIdx.x & 31, wid = threadIdx.x >> 5;
    if (lane == 0) { s1[wid] = sum; s2[wid] = sq; }
    __syncthreads();
    if (wid == 0) {
        sum = lane < 16 ? s1[lane] : 0.f;
        sq = lane < 16 ? s2[lane] : 0.f;
#pragma unroll
        for (int o = 16; o; o >>= 1) {
            sum += __shfl_xor_sync(~0u, sum, o);
            sq += __shfl_xor_sync(~0u, sq, o);
        }
        if (lane == 0) {
            const float inv_n = 1.f / (float)(CPG * HW);
            const float m = sum * inv_n;
            const float var = sq * inv_n - m * m;
            s1[0] = m;
            s2[0] = rsqrtf(var + EPS);
        }
    }
    __syncthreads();
    const float m = s1[0], r = s2[0];

    float ws[CPG], bs[CPG];
#pragma unroll
    for (int j = 0; j < CPG; j++) {
        const float wj = w[g * CPG + j];
        ws[j] = wj * r;
        bs[j] = b[g * CPG + j] - m * wj * r;
    }
    for (int p = threadIdx.x; p < HW; p += blockDim.x) {
        float o[CPG];
#pragma unroll
        for (int j = 0; j < CPG; j++) o[j] = rnd_tf32(xp[(size_t)j * HW + p] * ws[j] + bs[j]);
        float* dst = hT + ((size_t)batch * HW + p) * C + g * CPG;
#pragma unroll
        for (int j = 0; j < CPG; j += 4)
            *reinterpret_cast<float4*>(dst + j) = make_float4(o[j], o[j + 1], o[j + 2], o[j + 3]);
    }
}

// ---------------------------------------------------------------------------
// Row softmax over 4096 elements, in place; output tf32-rounded.
// ---------------------------------------------------------------------------
__global__ void __launch_bounds__(256) softmax_kernel(float* __restrict__ s) {
    float* row = s + (size_t)blockIdx.x * HW;
    const int t = threadIdx.x;
    float v[16];
    float mx = -1e30f;
#pragma unroll
    for (int i = 0; i < 16; i++) {
        v[i] = row[t + i * 256];
        mx = fmaxf(mx, v[i]);
    }
    __shared__ float shm[8], shs[8];
#pragma unroll
    for (int o = 16; o; o >>= 1) mx = fmaxf(mx, __shfl_xor_sync(~0u, mx, o));
    const int lane = t & 31, wid = t >> 5;
    if (lane == 0) shm[wid] = mx;
    __syncthreads();
    mx = shm[0];
#pragma unroll
    for (int i = 1; i < 8; i++) mx = fmaxf(mx, shm[i]);
    float sum = 0.f;
#pragma unroll
    for (int i = 0; i < 16; i++) { v[i] = __expf(v[i] - mx); sum += v[i]; }
#pragma unroll
    for (int o = 16; o; o >>= 1) sum += __shfl_xor_sync(~0u, sum, o);
    if (lane == 0) shs[wid] = sum;
    __syncthreads();
    sum = 0.f;
#pragma unroll
    for (int i = 0; i < 8; i++) sum += shs[i];
    const float inv = 1.f / sum;
#pragma unroll
    for (int i = 0; i < 16; i++) row[t + i * 256] = rnd_tf32(v[i] * inv);
}

// ---------------------------------------------------------------------------
extern "C" void kernel_launch(void* const* d_in, const int* in_sizes, int n_in,
                              void* d_out, int out_size) {
    const float* x   = (const float*)d_in[0];
    const float* gnw = (const float*)d_in[1];
    const float* gnb = (const float*)d_in[2];
    const float* qw  = (const float*)d_in[3];
    const float* qb  = (const float*)d_in[4];
    const float* kw  = (const float*)d_in[5];
    const float* kb  = (const float*)d_in[6];
    const float* vw  = (const float*)d_in[7];
    const float* vb  = (const float*)d_in[8];
    const float* pw  = (const float*)d_in[9];
    const float* pb  = (const float*)d_in[10];
    float* out = (float*)d_out;

    float *ht, *qt, *kt, *v, *s, *ot, *wr;
    cudaGetSymbolAddress((void**)&ht, g_ht);
    cudaGetSymbolAddress((void**)&qt, g_qt);
    cudaGetSymbolAddress((void**)&kt, g_kt);
    cudaGetSymbolAddress((void**)&v, g_v);
    cudaGetSymbolAddress((void**)&s, g_s);
    cudaGetSymbolAddress((void**)&ot, g_ot);
    cudaGetSymbolAddress((void**)&wr, g_wr);

    cudaFuncSetAttribute(tc_gemm<false, true,  false, true >, cudaFuncAttributeMaxDynamicSharedMemorySize, SMEM_BYTES);
    cudaFuncSetAttribute(tc_gemm<true,  false, false, true >, cudaFuncAttributeMaxDynamicSharedMemorySize, SMEM_BYTES);
    cudaFuncSetAttribute(tc_gemm<false, false, false, false>, cudaFuncAttributeMaxDynamicSharedMemorySize, SMEM_BYTES);
    cudaFuncSetAttribute(tc_gemm<false, false, false, true >, cudaFuncAttributeMaxDynamicSharedMemorySize, SMEM_BYTES);
    cudaFuncSetAttribute(tc_gemm<true,  false, true,  false>, cudaFuncAttributeMaxDynamicSharedMemorySize, SMEM_BYTES);

    const size_t sHC = (size_t)HW * C;
    const size_t sS = (size_t)HW * HW;
    const float scale = 0.044194173824159216f;  // 512^-0.5

    // 0) tf32-round weights; 1) GroupNorm -> hT (rounded)
    round_w<<<C * C / 256, 256>>>(qw, kw, vw, pw, wr);
    gn_kernel<<<BATCH * G, 512>>>(x, gnw, gnb, ht);

    const float* qwr = wr;
    const float* kwr = wr + (size_t)C * C;
    const float* vwr = wr + (size_t)2 * C * C;
    const float* pwr = wr + (size_t)3 * C * C;

    dim3 blk(256);
    // 2) qT/kT = hT @ W^T + bias(col):  M=HW, N=C, K=C
    dim3 g1(C / BN, HW / BM, BATCH);
    tc_gemm<false, true, false, true><<<g1, blk, SMEM_BYTES>>>(ht, qwr, qb, nullptr, qt, HW, C, C, 1.f, sHC, 0, sHC, 0);
    tc_gemm<false, true, false, true><<<g1, blk, SMEM_BYTES>>>(ht, kwr, kb, nullptr, kt, HW, C, C, 1.f, sHC, 0, sHC, 0);
    //    v = W @ h + bias(row):  M=C, N=HW, K=C   (B = hT)
    dim3 g2(HW / BN, C / BM, BATCH);
    tc_gemm<true, false, false, true><<<g2, blk, SMEM_BYTES>>>(vwr, ht, vb, nullptr, v, C, HW, C, 1.f, 0, sHC, sHC, 0);

    // 3) scores = qT @ kT^T * scale:  M=HW, N=HW, K=C
    dim3 g3(HW / BN, HW / BM, BATCH);
    tc_gemm<false, false, false, false><<<g3, blk, SMEM_BYTES>>>(qt, kt, nullptr, nullptr, s, HW, HW, C, scale, sHC, sHC, sS, 0);

    // 4) softmax rows (rounded output)
    softmax_kernel<<<BATCH * HW, 256>>>(s);

    // 5) oT = attn @ v^T:  M=HW(q), N=C(d), K=HW(k)
    dim3 g5(C / BN, HW / BM, BATCH);
    tc_gemm<false, false, false, true><<<g5, blk, SMEM_BYTES>>>(s, v, nullptr, nullptr, ot, HW, C, HW, 1.f, sS, sHC, sHC, 0);

    // 6) out = x + pw @ o + pb:  M=C, N=HW, K=C  (B = oT)
    dim3 g6(HW / BN, C / BM, BATCH);
    tc_gemm<true, false, true, false><<<g6, blk, SMEM_BYTES>>>(pwr, ot, pb, x, out, C, HW, C, 1.f, 0, sHC, sHC, sHC);
}